// round 1
// baseline (speedup 1.0000x reference)
#include <cuda_runtime.h>

// Problem shape (fixed by reference): query [B,I,M,K], support [B,I,M,K]
// out[b,i,j,m,n] = <q_norm[b,i,m,:], s_norm[b,j,n,:]>
static constexpr int B = 4;
static constexpr int I = 25;   // = j count
static constexpr int M = 128;  // = n count
static constexpr int K = 64;

static constexpr int PITCH = 132;            // smem pitch (floats) for [K][M] tiles; %4==0 for float4, %32==4
static constexpr int TILE_FLOATS = K * PITCH;
static constexpr int SMEM_FLOATS = 2 * TILE_FLOATS + 2 * M;
static constexpr int SMEM_BYTES  = SMEM_FLOATS * (int)sizeof(float);

__global__ void __launch_bounds__(256, 2)
cosine_relation_kernel(const float* __restrict__ query,
                       const float* __restrict__ support,
                       float* __restrict__ out) {
    extern __shared__ float smem[];
    float* Qs   = smem;                    // [K][PITCH] transposed: Qs[k*PITCH + m]
    float* Ss   = smem + TILE_FLOATS;      // [K][PITCH]
    float* invQ = smem + 2 * TILE_FLOATS;  // [M]
    float* invS = invQ + M;                // [M]

    const int j = blockIdx.x;
    const int i = blockIdx.y;
    const int b = blockIdx.z;
    const int tid = threadIdx.x;

    const float* gQ = query   + (size_t)((b * I + i) * M) * K;
    const float* gS = support + (size_t)((b * I + j) * M) * K;

    // Load tiles, transposing to [k][m] in smem. Global reads fully coalesced.
    #pragma unroll 8
    for (int e = tid; e < M * K; e += 256) {
        const int m = e >> 6;       // e / K
        const int k = e & (K - 1);  // e % K
        Qs[k * PITCH + m] = gQ[e];
        Ss[k * PITCH + m] = gS[e];
    }
    __syncthreads();

    // Per-row inverse L2 norms (threads 0..127 -> Q rows, 128..255 -> S rows)
    if (tid < M) {
        float s = 0.f;
        #pragma unroll
        for (int k = 0; k < K; k++) {
            const float v = Qs[k * PITCH + tid];
            s = fmaf(v, v, s);
        }
        invQ[tid] = 1.f / fmaxf(sqrtf(s), 1e-12f);
    } else {
        const int n = tid - M;
        float s = 0.f;
        #pragma unroll
        for (int k = 0; k < K; k++) {
            const float v = Ss[k * PITCH + n];
            s = fmaf(v, v, s);
        }
        invS[n] = 1.f / fmaxf(sqrtf(s), 1e-12f);
    }
    __syncthreads();

    // 16x16 thread grid, each thread computes an 8x8 output block.
    const int tx = tid & 15;
    const int ty = tid >> 4;
    const int m0 = ty * 8;
    const int n0 = tx * 8;

    float acc[8][8];
    #pragma unroll
    for (int r = 0; r < 8; r++)
        #pragma unroll
        for (int c = 0; c < 8; c++)
            acc[r][c] = 0.f;

    #pragma unroll 8
    for (int k = 0; k < K; k++) {
        const float4 a0 = *(const float4*)&Qs[k * PITCH + m0];
        const float4 a1 = *(const float4*)&Qs[k * PITCH + m0 + 4];
        const float4 b0 = *(const float4*)&Ss[k * PITCH + n0];
        const float4 b1 = *(const float4*)&Ss[k * PITCH + n0 + 4];
        const float a[8] = {a0.x, a0.y, a0.z, a0.w, a1.x, a1.y, a1.z, a1.w};
        const float bb[8] = {b0.x, b0.y, b0.z, b0.w, b1.x, b1.y, b1.z, b1.w};
        #pragma unroll
        for (int r = 0; r < 8; r++)
            #pragma unroll
            for (int c = 0; c < 8; c++)
                acc[r][c] = fmaf(a[r], bb[c], acc[r][c]);
    }

    // Epilogue: fold inverse norms, coalesced float4 stores.
    float isv[8];
    #pragma unroll
    for (int c = 0; c < 8; c++) isv[c] = invS[n0 + c];

    float* gO = out + ((size_t)((b * I + i) * I + j) * M) * M;
    #pragma unroll
    for (int r = 0; r < 8; r++) {
        const float iq = invQ[m0 + r];
        float4 v0, v1;
        v0.x = acc[r][0] * iq * isv[0];
        v0.y = acc[r][1] * iq * isv[1];
        v0.z = acc[r][2] * iq * isv[2];
        v0.w = acc[r][3] * iq * isv[3];
        v1.x = acc[r][4] * iq * isv[4];
        v1.y = acc[r][5] * iq * isv[5];
        v1.z = acc[r][6] * iq * isv[6];
        v1.w = acc[r][7] * iq * isv[7];
        float* row = gO + (size_t)(m0 + r) * M + n0;
        *(float4*)(row)     = v0;
        *(float4*)(row + 4) = v1;
    }
}

extern "C" void kernel_launch(void* const* d_in, const int* in_sizes, int n_in,
                              void* d_out, int out_size) {
    const float* query   = (const float*)d_in[0];
    const float* support = (const float*)d_in[1];
    float* out = (float*)d_out;

    cudaFuncSetAttribute(cosine_relation_kernel,
                         cudaFuncAttributeMaxDynamicSharedMemorySize, SMEM_BYTES);

    dim3 grid(I, I, B);   // x = j, y = i, z = b
    dim3 block(256);
    cosine_relation_kernel<<<grid, block, SMEM_BYTES>>>(query, support, out);
}

// round 3
// speedup vs baseline: 1.6223x; 1.6223x over previous
#include <cuda_runtime.h>
#include <cstdint>

// out[b,i,j,m,n] = <q_norm[b,i,m,:], s_norm[b,j,n,:]>
// q,s: [4,25,128,64] fp32; out: [4,25,25,128,128] fp32
static constexpr int B_ = 4, I_ = 25, M_ = 128, K_ = 64;
static constexpr int NTILES = B_ * I_ * I_;       // 2500
static constexpr int PITCH = 68;                   // smem row pitch in words (4g+tg conflict-free)
static constexpr int TILE_WORDS = M_ * PITCH;      // 8704
static constexpr int SMEM_BYTES = 2 * TILE_WORDS * 4;  // 69632 B

__device__ __forceinline__ uint32_t f2tf32(float f) {
    uint32_t r;
    asm("cvt.rna.tf32.f32 %0, %1;" : "=r"(r) : "f"(f));
    return r;
}

__device__ __forceinline__ void mma_tf32(float* c, const uint32_t* a, const uint32_t* b) {
    asm volatile(
        "mma.sync.aligned.m16n8k8.row.col.f32.tf32.tf32.f32 "
        "{%0,%1,%2,%3}, {%4,%5,%6,%7}, {%8,%9}, {%0,%1,%2,%3};"
        : "+f"(c[0]), "+f"(c[1]), "+f"(c[2]), "+f"(c[3])
        : "r"(a[0]), "r"(a[1]), "r"(a[2]), "r"(a[3]), "r"(b[0]), "r"(b[1]));
}

__global__ void __launch_bounds__(256, 2)
cosine_mma_kernel(const float* __restrict__ query,
                  const float* __restrict__ support,
                  float* __restrict__ out) {
    extern __shared__ uint32_t sm[];
    uint32_t* Qs = sm;                 // [128][PITCH] tf32 (normalized)
    uint32_t* Ss = sm + TILE_WORDS;    // [128][PITCH]

    const int tid = threadIdx.x;
    const int idx = blockIdx.x;
    const int j = idx % I_;
    const int i = (idx / I_) % I_;
    const int b = idx / (I_ * I_);

    // ---- Stage: thread t<128 -> Q row t; t>=128 -> S row t-128.
    // Load 64 floats, fp32 L2-normalize, convert to tf32, store to smem.
    {
        const int r = tid & 127;
        const float4* src = (tid < M_)
            ? (const float4*)(query   + ((size_t)(b * I_ + i) * M_ + r) * K_)
            : (const float4*)(support + ((size_t)(b * I_ + j) * M_ + r) * K_);
        uint32_t* dst = ((tid < M_) ? Qs : Ss) + r * PITCH;

        float4 v[16];
        float s = 0.f;
        #pragma unroll
        for (int u = 0; u < 16; u++) {
            v[u] = src[u];
            s = fmaf(v[u].x, v[u].x, s);
            s = fmaf(v[u].y, v[u].y, s);
            s = fmaf(v[u].z, v[u].z, s);
            s = fmaf(v[u].w, v[u].w, s);
        }
        const float inv = 1.0f / fmaxf(sqrtf(s), 1e-12f);
        #pragma unroll
        for (int u = 0; u < 16; u++) {
            uint4 w;
            w.x = f2tf32(v[u].x * inv);
            w.y = f2tf32(v[u].y * inv);
            w.z = f2tf32(v[u].z * inv);
            w.w = f2tf32(v[u].w * inv);
            *(uint4*)(dst + u * 4) = w;
        }
    }
    __syncthreads();

    // ---- Mainloop: warp grid 2(m) x 4(n); warp tile 64x32 = 4x4 m16n8k8.
    const int wid = tid >> 5;
    const int lane = tid & 31;
    const int g = lane >> 2;       // group id (row within fragment)
    const int tg = lane & 3;       // thread-in-group (k / col pair)
    const int mwBase = (wid & 1) * 64;
    const int nwBase = (wid >> 1) * 32;

    float c[4][4][4];
    #pragma unroll
    for (int mt = 0; mt < 4; mt++)
        #pragma unroll
        for (int nt = 0; nt < 4; nt++)
            #pragma unroll
            for (int e = 0; e < 4; e++)
                c[mt][nt][e] = 0.f;

    #pragma unroll
    for (int ks = 0; ks < 8; ks++) {
        const int k0 = ks * 8 + tg;
        const int k1 = k0 + 4;

        uint32_t a[4][4], bf[4][2];
        #pragma unroll
        for (int mt = 0; mt < 4; mt++) {
            const int r0 = mwBase + mt * 16 + g;
            a[mt][0] = Qs[r0 * PITCH + k0];
            a[mt][1] = Qs[(r0 + 8) * PITCH + k0];
            a[mt][2] = Qs[r0 * PITCH + k1];
            a[mt][3] = Qs[(r0 + 8) * PITCH + k1];
        }
        #pragma unroll
        for (int nt = 0; nt < 4; nt++) {
            const int rn = nwBase + nt * 8 + g;
            bf[nt][0] = Ss[rn * PITCH + k0];
            bf[nt][1] = Ss[rn * PITCH + k1];
        }
        #pragma unroll
        for (int mt = 0; mt < 4; mt++)
            #pragma unroll
            for (int nt = 0; nt < 4; nt++)
                mma_tf32(c[mt][nt], a[mt], bf[nt]);
    }

    // ---- Epilogue: direct float2 stores (quad-contiguous 32B sectors).
    float* gO = out + (size_t)idx * (M_ * M_);
    #pragma unroll
    for (int mt = 0; mt < 4; mt++) {
        const int r0 = mwBase + mt * 16 + g;
        #pragma unroll
        for (int nt = 0; nt < 4; nt++) {
            const int col = nwBase + nt * 8 + tg * 2;
            *(float2*)(gO + (size_t)r0 * M_ + col)       = make_float2(c[mt][nt][0], c[mt][nt][1]);
            *(float2*)(gO + (size_t)(r0 + 8) * M_ + col) = make_float2(c[mt][nt][2], c[mt][nt][3]);
        }
    }
}

extern "C" void kernel_launch(void* const* d_in, const int* in_sizes, int n_in,
                              void* d_out, int out_size) {
    const float* query   = (const float*)d_in[0];
    const float* support = (const float*)d_in[1];
    float* out = (float*)d_out;

    cudaFuncSetAttribute(cosine_mma_kernel,
                         cudaFuncAttributeMaxDynamicSharedMemorySize, SMEM_BYTES);

    cosine_mma_kernel<<<NTILES, 256, SMEM_BYTES>>>(query, support, out);
}

// round 4
// speedup vs baseline: 1.8775x; 1.1573x over previous
#include <cuda_runtime.h>
#include <cuda_fp16.h>
#include <cstdint>

// out[b,i,j,m,n] = <q_norm[b,i,m,:], s_norm[b,j,n,:]>
// q,s: [4,25,128,64] fp32; out: [4,25,25,128,128] fp32
static constexpr int B_ = 4, I_ = 25, M_ = 128, K_ = 64;
static constexpr int NTILES = B_ * I_ * I_;        // 2500
static constexpr int PITCH_H = 72;                  // halves per row (144 B; bank = 4r+c, conflict-free)
static constexpr int TILE_BYTES = M_ * PITCH_H * 2; // 18432
static constexpr int SMEM_BYTES = 2 * TILE_BYTES;   // 36864

__device__ __forceinline__ uint32_t smem_u32(const void* p) {
    uint32_t a;
    asm("{ .reg .u64 t; cvta.to.shared.u64 t, %1; cvt.u32.u64 %0, t; }" : "=r"(a) : "l"(p));
    return a;
}

__device__ __forceinline__ void ldsm_x4(uint32_t* r, uint32_t addr) {
    asm volatile("ldmatrix.sync.aligned.m8n8.x4.shared.b16 {%0,%1,%2,%3}, [%4];"
                 : "=r"(r[0]), "=r"(r[1]), "=r"(r[2]), "=r"(r[3]) : "r"(addr));
}

__device__ __forceinline__ void mma_f16(float* c, const uint32_t* a, const uint32_t* b) {
    asm volatile(
        "mma.sync.aligned.m16n8k16.row.col.f32.f16.f16.f32 "
        "{%0,%1,%2,%3}, {%4,%5,%6,%7}, {%8,%9}, {%0,%1,%2,%3};"
        : "+f"(c[0]), "+f"(c[1]), "+f"(c[2]), "+f"(c[3])
        : "r"(a[0]), "r"(a[1]), "r"(a[2]), "r"(a[3]), "r"(b[0]), "r"(b[1]));
}

__global__ void __launch_bounds__(256, 2)
cosine_hmma_kernel(const float* __restrict__ query,
                   const float* __restrict__ support,
                   float* __restrict__ out) {
    extern __shared__ __half sm[];
    __half* Qh = sm;                       // [128][PITCH_H] normalized fp16
    __half* Sh = sm + M_ * PITCH_H;        // [128][PITCH_H]

    const int tid = threadIdx.x;
    const int idx = blockIdx.x;
    const int j = idx % I_;
    const int i = (idx / I_) % I_;
    const int b = idx / (I_ * I_);

    // ---- Stage: thread t<128 -> Q row t; t>=128 -> S row t-128.
    {
        const int r = tid & 127;
        const float4* src = (tid < M_)
            ? (const float4*)(query   + ((size_t)(b * I_ + i) * M_ + r) * K_)
            : (const float4*)(support + ((size_t)(b * I_ + j) * M_ + r) * K_);
        __half* dst = ((tid < M_) ? Qh : Sh) + r * PITCH_H;

        float4 v[16];
        float s = 0.f;
        #pragma unroll
        for (int u = 0; u < 16; u++) {
            v[u] = src[u];
            s = fmaf(v[u].x, v[u].x, s);
            s = fmaf(v[u].y, v[u].y, s);
            s = fmaf(v[u].z, v[u].z, s);
            s = fmaf(v[u].w, v[u].w, s);
        }
        const float inv = 1.0f / fmaxf(sqrtf(s), 1e-12f);
        #pragma unroll
        for (int u = 0; u < 8; u++) {
            // 8 floats -> 8 halves -> one 16B store
            const float4 p = v[2 * u], q = v[2 * u + 1];
            __half2 h0 = __floats2half2_rn(p.x * inv, p.y * inv);
            __half2 h1 = __floats2half2_rn(p.z * inv, p.w * inv);
            __half2 h2 = __floats2half2_rn(q.x * inv, q.y * inv);
            __half2 h3 = __floats2half2_rn(q.z * inv, q.w * inv);
            uint4 w;
            w.x = *(uint32_t*)&h0; w.y = *(uint32_t*)&h1;
            w.z = *(uint32_t*)&h2; w.w = *(uint32_t*)&h3;
            *(uint4*)(dst + u * 8) = w;
        }
    }
    __syncthreads();

    // ---- Mainloop: 8 warps in 2(m) x 4(n); warp tile 64x32; 4 k-steps of 16.
    const int wid = tid >> 5;
    const int lane = tid & 31;
    const int g = lane >> 2;
    const int tg = lane & 3;
    const int mwBase = (wid & 1) * 64;
    const int nwBase = (wid >> 1) * 32;

    // Per-thread ldmatrix source addresses (slot = lane>>3).
    const int slot = lane >> 3;
    const int l7 = lane & 7;
    // A: slot0 rows0-7/k0-7 (a0), slot1 rows8-15/k0-7 (a1), slot2 rows0-7/k8-15 (a2), slot3 rows8-15/k8-15 (a3)
    const uint32_t baseA = smem_u32(Qh) +
        ((uint32_t)(mwBase + (slot & 1) * 8 + l7) * PITCH_H + (slot >> 1) * 8) * 2;
    // B: slot0 n0-7/k0-7 (b0 even nt), slot1 n0-7/k8-15 (b1 even), slot2 n8-15/k0-7 (b0 odd), slot3 n8-15/k8-15 (b1 odd)
    const uint32_t baseB = smem_u32(Sh) +
        ((uint32_t)(nwBase + (slot >> 1) * 8 + l7) * PITCH_H + (slot & 1) * 8) * 2;

    float c[4][4][4];
    #pragma unroll
    for (int mt = 0; mt < 4; mt++)
        #pragma unroll
        for (int nt = 0; nt < 4; nt++)
            #pragma unroll
            for (int e = 0; e < 4; e++)
                c[mt][nt][e] = 0.f;

    #pragma unroll
    for (int ks = 0; ks < 4; ks++) {
        const uint32_t kOff = (uint32_t)ks * 16 * 2;  // 16 halves = 32 B per k-step

        uint32_t a[4][4];
        #pragma unroll
        for (int mt = 0; mt < 4; mt++)
            ldsm_x4(a[mt], baseA + (uint32_t)mt * 16 * PITCH_H * 2 + kOff);

        uint32_t bf[2][4];
        #pragma unroll
        for (int np = 0; np < 2; np++)
            ldsm_x4(bf[np], baseB + (uint32_t)np * 16 * PITCH_H * 2 + kOff);

        #pragma unroll
        for (int mt = 0; mt < 4; mt++)
            #pragma unroll
            for (int nt = 0; nt < 4; nt++)
                mma_f16(c[mt][nt], a[mt], &bf[nt >> 1][(nt & 1) * 2]);
    }

    // ---- Epilogue: float2 stores (quad-contiguous 32B sectors).
    float* gO = out + (size_t)idx * (M_ * M_);
    #pragma unroll
    for (int mt = 0; mt < 4; mt++) {
        const int r0 = mwBase + mt * 16 + g;
        #pragma unroll
        for (int nt = 0; nt < 4; nt++) {
            const int col = nwBase + nt * 8 + tg * 2;
            *(float2*)(gO + (size_t)r0 * M_ + col)       = make_float2(c[mt][nt][0], c[mt][nt][1]);
            *(float2*)(gO + (size_t)(r0 + 8) * M_ + col) = make_float2(c[mt][nt][2], c[mt][nt][3]);
        }
    }
}

extern "C" void kernel_launch(void* const* d_in, const int* in_sizes, int n_in,
                              void* d_out, int out_size) {
    const float* query   = (const float*)d_in[0];
    const float* support = (const float*)d_in[1];
    float* out = (float*)d_out;

    cudaFuncSetAttribute(cosine_hmma_kernel,
                         cudaFuncAttributeMaxDynamicSharedMemorySize, SMEM_BYTES);

    cosine_hmma_kernel<<<NTILES, 256, SMEM_BYTES>>>(query, support, out);
}

// round 5
// speedup vs baseline: 3.1256x; 1.6648x over previous
#include <cuda_runtime.h>
#include <cuda_fp16.h>
#include <cstdint>

// out[b,i,j,m,n] = <q_norm[b,i,m,:], s_norm[b,j,n,:]>
// q,s: [4,25,128,64] fp32; out: [4,25,25,128,128] fp32
static constexpr int B_ = 4, I_ = 25, M_ = 128, K_ = 64;
static constexpr int NROWS = B_ * I_ * M_;          // 12800 rows per tensor
static constexpr int G_ = 5;                        // j-tiles per CTA
static constexpr int NCTAS = B_ * I_ * (I_ / G_);   // 500

static constexpr int PITCH_H = 72;                  // halves per smem row (144 B)
static constexpr int TILE_BYTES = M_ * PITCH_H * 2; // 18432
static constexpr int SMEM_BYTES = 3 * TILE_BYTES;   // Q + 2x S = 55296

// Pre-normalized fp16 operands (written by normalize_kernel)
__device__ __half d_qh[NROWS * K_];
__device__ __half d_sh[NROWS * K_];

__device__ __forceinline__ uint32_t smem_u32(const void* p) {
    uint32_t a;
    asm("{ .reg .u64 t; cvta.to.shared.u64 t, %1; cvt.u32.u64 %0, t; }" : "=r"(a) : "l"(p));
    return a;
}

__device__ __forceinline__ void ldsm_x4(uint32_t* r, uint32_t addr) {
    asm volatile("ldmatrix.sync.aligned.m8n8.x4.shared.b16 {%0,%1,%2,%3}, [%4];"
                 : "=r"(r[0]), "=r"(r[1]), "=r"(r[2]), "=r"(r[3]) : "r"(addr));
}

__device__ __forceinline__ void mma_f16(float* c, const uint32_t* a, const uint32_t* b) {
    asm volatile(
        "mma.sync.aligned.m16n8k16.row.col.f32.f16.f16.f32 "
        "{%0,%1,%2,%3}, {%4,%5,%6,%7}, {%8,%9}, {%0,%1,%2,%3};"
        : "+f"(c[0]), "+f"(c[1]), "+f"(c[2]), "+f"(c[3])
        : "r"(a[0]), "r"(a[1]), "r"(a[2]), "r"(a[3]), "r"(b[0]), "r"(b[1]));
}

__device__ __forceinline__ void cp16(uint32_t dst, const void* src) {
    asm volatile("cp.async.cg.shared.global [%0], [%1], 16;" :: "r"(dst), "l"(src));
}
__device__ __forceinline__ void cp_commit() {
    asm volatile("cp.async.commit_group;" ::: "memory");
}
__device__ __forceinline__ void cp_wait0() {
    asm volatile("cp.async.wait_group 0;" ::: "memory");
}

// Stage one 128x64 fp16 tile (row-major, 128 B/row) into padded smem via cp.async.
__device__ __forceinline__ void stage_tile(uint32_t dstBase, const __half* srcTile, int tid) {
    #pragma unroll
    for (int u = 0; u < 4; u++) {
        const int chunk = u * 256 + tid;         // 0..1023 16B-chunks
        const int row = chunk >> 3;
        const int c16 = chunk & 7;
        cp16(dstBase + (uint32_t)row * (PITCH_H * 2) + c16 * 16,
             srcTile + (size_t)row * K_ + c16 * 8);
    }
}

// ---------------- Kernel 1: normalize to fp16 ----------------
__global__ void __launch_bounds__(256)
normalize_kernel(const float* __restrict__ q, const float* __restrict__ s) {
    const int r = blockIdx.x * 256 + threadIdx.x;  // 0..25599
    const bool isQ = r < NROWS;
    const int rr = isQ ? r : r - NROWS;
    const float4* src = (const float4*)((isQ ? q : s) + (size_t)rr * K_);
    __half* dst = (isQ ? d_qh : d_sh) + (size_t)rr * K_;

    float4 v[16];
    float sum = 0.f;
    #pragma unroll
    for (int u = 0; u < 16; u++) {
        v[u] = src[u];
        sum = fmaf(v[u].x, v[u].x, sum);
        sum = fmaf(v[u].y, v[u].y, sum);
        sum = fmaf(v[u].z, v[u].z, sum);
        sum = fmaf(v[u].w, v[u].w, sum);
    }
    const float inv = 1.0f / fmaxf(sqrtf(sum), 1e-12f);
    #pragma unroll
    for (int u = 0; u < 8; u++) {
        const float4 p = v[2 * u], w = v[2 * u + 1];
        __half2 h0 = __floats2half2_rn(p.x * inv, p.y * inv);
        __half2 h1 = __floats2half2_rn(p.z * inv, p.w * inv);
        __half2 h2 = __floats2half2_rn(w.x * inv, w.y * inv);
        __half2 h3 = __floats2half2_rn(w.z * inv, w.w * inv);
        uint4 o;
        o.x = *(uint32_t*)&h0; o.y = *(uint32_t*)&h1;
        o.z = *(uint32_t*)&h2; o.w = *(uint32_t*)&h3;
        *(uint4*)(dst + u * 8) = o;
    }
}

// ---------------- Kernel 2: grouped GEMM ----------------
__global__ void __launch_bounds__(256, 2)
cosine_gemm_kernel(float* __restrict__ out) {
    extern __shared__ __half sm[];
    const uint32_t qBase = smem_u32(sm);                   // Q tile
    const uint32_t sBase = qBase + TILE_BYTES;             // S double buffer [2]

    const int tid = threadIdx.x;
    const int cidx = blockIdx.x;
    const int jg = cidx % (I_ / G_);
    const int i  = (cidx / (I_ / G_)) % I_;
    const int b  = cidx / ((I_ / G_) * I_);

    const __half* qTile = d_qh + (size_t)(b * I_ + i) * (M_ * K_);
    const __half* sTile0 = d_sh + (size_t)(b * I_ + jg * G_) * (M_ * K_);

    // Prologue: stage Q and S0
    stage_tile(qBase, qTile, tid);
    stage_tile(sBase, sTile0, tid);
    cp_commit();
    cp_wait0();
    __syncthreads();

    // Warp/lane geometry (same fragment mapping as R4)
    const int wid = tid >> 5;
    const int lane = tid & 31;
    const int g = lane >> 2;
    const int tg = lane & 3;
    const int mwBase = (wid & 1) * 64;
    const int nwBase = (wid >> 1) * 32;
    const int slot = lane >> 3;
    const int l7 = lane & 7;

    const uint32_t baseA = qBase +
        ((uint32_t)(mwBase + (slot & 1) * 8 + l7) * PITCH_H + (slot >> 1) * 8) * 2;
    const uint32_t baseBrel =
        ((uint32_t)(nwBase + (slot >> 1) * 8 + l7) * PITCH_H + (slot & 1) * 8) * 2;

    float* gOi = out + (size_t)((b * I_ + i) * I_ + jg * G_) * (M_ * M_);

    for (int t = 0; t < G_; t++) {
        // Prefetch next S into alternate buffer
        if (t + 1 < G_) {
            stage_tile(sBase + ((t + 1) & 1) * TILE_BYTES,
                       sTile0 + (size_t)(t + 1) * (M_ * K_), tid);
            cp_commit();
        }

        const uint32_t baseB = sBase + (t & 1) * TILE_BYTES + baseBrel;

        float c[4][4][4];
        #pragma unroll
        for (int mt = 0; mt < 4; mt++)
            #pragma unroll
            for (int nt = 0; nt < 4; nt++)
                #pragma unroll
                for (int e = 0; e < 4; e++)
                    c[mt][nt][e] = 0.f;

        #pragma unroll
        for (int ks = 0; ks < 4; ks++) {
            const uint32_t kOff = (uint32_t)ks * 16 * 2;

            uint32_t a[4][4];
            #pragma unroll
            for (int mt = 0; mt < 4; mt++)
                ldsm_x4(a[mt], baseA + (uint32_t)mt * 16 * PITCH_H * 2 + kOff);

            uint32_t bf[2][4];
            #pragma unroll
            for (int np = 0; np < 2; np++)
                ldsm_x4(bf[np], baseB + (uint32_t)np * 16 * PITCH_H * 2 + kOff);

            #pragma unroll
            for (int mt = 0; mt < 4; mt++)
                #pragma unroll
                for (int nt = 0; nt < 4; nt++)
                    mma_f16(c[mt][nt], a[mt], &bf[nt >> 1][(nt & 1) * 2]);
        }

        // Epilogue
        float* gO = gOi + (size_t)t * (M_ * M_);
        #pragma unroll
        for (int mt = 0; mt < 4; mt++) {
            const int r0 = mwBase + mt * 16 + g;
            #pragma unroll
            for (int nt = 0; nt < 4; nt++) {
                const int col = nwBase + nt * 8 + tg * 2;
                *(float2*)(gO + (size_t)r0 * M_ + col)       = make_float2(c[mt][nt][0], c[mt][nt][1]);
                *(float2*)(gO + (size_t)(r0 + 8) * M_ + col) = make_float2(c[mt][nt][2], c[mt][nt][3]);
            }
        }

        if (t + 1 < G_) {
            cp_wait0();
            __syncthreads();
        }
    }
}

extern "C" void kernel_launch(void* const* d_in, const int* in_sizes, int n_in,
                              void* d_out, int out_size) {
    const float* query   = (const float*)d_in[0];
    const float* support = (const float*)d_in[1];
    float* out = (float*)d_out;

    cudaFuncSetAttribute(cosine_gemm_kernel,
                         cudaFuncAttributeMaxDynamicSharedMemorySize, SMEM_BYTES);

    normalize_kernel<<<(2 * NROWS) / 256, 256>>>(query, support);
    cosine_gemm_kernel<<<NCTAS, 256, SMEM_BYTES>>>(out);
}

// round 6
// speedup vs baseline: 3.2566x; 1.0419x over previous
#include <cuda_runtime.h>
#include <cuda_fp16.h>
#include <cstdint>

// out[b,i,j,m,n] = <q_norm[b,i,m,:], s_norm[b,j,n,:]>
// q,s: [4,25,128,64] fp32; out: [4,25,25,128,128] fp32
static constexpr int B_ = 4, I_ = 25, M_ = 128, K_ = 64;
static constexpr int NROWS = B_ * I_ * M_;          // 12800 rows per tensor
static constexpr int NTILES = B_ * I_ * I_;         // 2500
static constexpr int NC = 304;                      // persistent CTAs (2/SM x 152 SMs)

static constexpr int PITCH_H = 72;                  // halves per smem row (144 B)
static constexpr int TILE_BYTES = M_ * PITCH_H * 2; // 18432
static constexpr int SMEM_BYTES = 4 * TILE_BYTES;   // Q[2] + S[2] = 73728

// Pre-normalized fp16 operands (written by normalize_kernel)
__device__ __half d_qh[NROWS * K_];
__device__ __half d_sh[NROWS * K_];

__device__ __forceinline__ uint32_t smem_u32(const void* p) {
    uint32_t a;
    asm("{ .reg .u64 t; cvta.to.shared.u64 t, %1; cvt.u32.u64 %0, t; }" : "=r"(a) : "l"(p));
    return a;
}

__device__ __forceinline__ void ldsm_x4(uint32_t* r, uint32_t addr) {
    asm volatile("ldmatrix.sync.aligned.m8n8.x4.shared.b16 {%0,%1,%2,%3}, [%4];"
                 : "=r"(r[0]), "=r"(r[1]), "=r"(r[2]), "=r"(r[3]) : "r"(addr));
}

__device__ __forceinline__ void mma_f16(float* c, const uint32_t* a, const uint32_t* b) {
    asm volatile(
        "mma.sync.aligned.m16n8k16.row.col.f32.f16.f16.f32 "
        "{%0,%1,%2,%3}, {%4,%5,%6,%7}, {%8,%9}, {%0,%1,%2,%3};"
        : "+f"(c[0]), "+f"(c[1]), "+f"(c[2]), "+f"(c[3])
        : "r"(a[0]), "r"(a[1]), "r"(a[2]), "r"(a[3]), "r"(b[0]), "r"(b[1]));
}

__device__ __forceinline__ void cp16(uint32_t dst, const void* src) {
    asm volatile("cp.async.cg.shared.global [%0], [%1], 16;" :: "r"(dst), "l"(src));
}
__device__ __forceinline__ void cp_commit() {
    asm volatile("cp.async.commit_group;" ::: "memory");
}
__device__ __forceinline__ void cp_wait0() {
    asm volatile("cp.async.wait_group 0;" ::: "memory");
}

// Stage one 128x64 fp16 tile (row-major, 128 B/row) into padded smem via cp.async.
__device__ __forceinline__ void stage_tile(uint32_t dstBase, const __half* srcTile, int tid) {
    #pragma unroll
    for (int u = 0; u < 4; u++) {
        const int chunk = u * 256 + tid;         // 0..1023 16B-chunks
        const int row = chunk >> 3;
        const int c16 = chunk & 7;
        cp16(dstBase + (uint32_t)row * (PITCH_H * 2) + c16 * 16,
             srcTile + (size_t)row * K_ + c16 * 8);
    }
}

// ---------------- Kernel 1: normalize to fp16 ----------------
__global__ void __launch_bounds__(256)
normalize_kernel(const float* __restrict__ q, const float* __restrict__ s) {
    const int r = blockIdx.x * 256 + threadIdx.x;  // 0..25599
    const bool isQ = r < NROWS;
    const int rr = isQ ? r : r - NROWS;
    const float4* src = (const float4*)((isQ ? q : s) + (size_t)rr * K_);
    __half* dst = (isQ ? d_qh : d_sh) + (size_t)rr * K_;

    float4 v[16];
    float sum = 0.f;
    #pragma unroll
    for (int u = 0; u < 16; u++) {
        v[u] = src[u];
        sum = fmaf(v[u].x, v[u].x, sum);
        sum = fmaf(v[u].y, v[u].y, sum);
        sum = fmaf(v[u].z, v[u].z, sum);
        sum = fmaf(v[u].w, v[u].w, sum);
    }
    const float inv = 1.0f / fmaxf(sqrtf(sum), 1e-12f);
    #pragma unroll
    for (int u = 0; u < 8; u++) {
        const float4 p = v[2 * u], w = v[2 * u + 1];
        __half2 h0 = __floats2half2_rn(p.x * inv, p.y * inv);
        __half2 h1 = __floats2half2_rn(p.z * inv, p.w * inv);
        __half2 h2 = __floats2half2_rn(w.x * inv, w.y * inv);
        __half2 h3 = __floats2half2_rn(w.z * inv, w.w * inv);
        uint4 o;
        o.x = *(uint32_t*)&h0; o.y = *(uint32_t*)&h1;
        o.z = *(uint32_t*)&h2; o.w = *(uint32_t*)&h3;
        *(uint4*)(dst + u * 8) = o;
    }
}

// ---------------- Kernel 2: persistent grouped GEMM ----------------
__global__ void __launch_bounds__(256, 2)
cosine_gemm_kernel(float* __restrict__ out) {
    extern __shared__ __half sm[];
    const uint32_t qBase = smem_u32(sm);                 // Q double buffer [2]
    const uint32_t sBase = qBase + 2 * TILE_BYTES;       // S double buffer [2]

    const int tid = threadIdx.x;
    const int cidx = blockIdx.x;

    // Contiguous chunk of the tile linearization t = (b*I+i)*I + j
    const int t0 = (int)((long long)cidx * NTILES / NC);
    const int t1 = (int)((long long)(cidx + 1) * NTILES / NC);
    if (t0 >= t1) return;

    // Warp/lane geometry (fragment mapping as R4/R5)
    const int wid = tid >> 5;
    const int lane = tid & 31;
    const int g = lane >> 2;
    const int tg = lane & 3;
    const int mwBase = (wid & 1) * 64;
    const int nwBase = (wid >> 1) * 32;
    const int slot = lane >> 3;
    const int l7 = lane & 7;

    const uint32_t baseArel =
        ((uint32_t)(mwBase + (slot & 1) * 8 + l7) * PITCH_H + (slot >> 1) * 8) * 2;
    const uint32_t baseBrel =
        ((uint32_t)(nwBase + (slot >> 1) * 8 + l7) * PITCH_H + (slot & 1) * 8) * 2;

    // Prologue: stage Q(t0) into q-buf 0 and S(t0) into s-buf 0
    int bi = t0 / I_;                                  // (b*I + i)
    stage_tile(qBase, d_qh + (size_t)bi * (M_ * K_), tid);
    stage_tile(sBase, d_sh + (size_t)((bi / I_) * I_ + (t0 % I_)) * (M_ * K_), tid);
    cp_commit();
    cp_wait0();
    __syncthreads();

    int qcur = 0;

    for (int t = t0; t < t1; t++) {
        const int sp = (t - t0) & 1;
        bool qflip = false;

        // Prefetch next tile's operands
        if (t + 1 < t1) {
            const int nbi = (t + 1) / I_;
            if (nbi != bi) {
                stage_tile(qBase + (qcur ^ 1) * TILE_BYTES,
                           d_qh + (size_t)nbi * (M_ * K_), tid);
                qflip = true;
            }
            stage_tile(sBase + (sp ^ 1) * TILE_BYTES,
                       d_sh + (size_t)((nbi / I_) * I_ + ((t + 1) % I_)) * (M_ * K_), tid);
            cp_commit();
        }

        const uint32_t baseA = qBase + qcur * TILE_BYTES + baseArel;
        const uint32_t baseB = sBase + sp * TILE_BYTES + baseBrel;

        float c[4][4][4];
        #pragma unroll
        for (int mt = 0; mt < 4; mt++)
            #pragma unroll
            for (int nt = 0; nt < 4; nt++)
                #pragma unroll
                for (int e = 0; e < 4; e++)
                    c[mt][nt][e] = 0.f;

        #pragma unroll
        for (int ks = 0; ks < 4; ks++) {
            const uint32_t kOff = (uint32_t)ks * 16 * 2;

            uint32_t a[4][4];
            #pragma unroll
            for (int mt = 0; mt < 4; mt++)
                ldsm_x4(a[mt], baseA + (uint32_t)mt * 16 * PITCH_H * 2 + kOff);

            uint32_t bf[2][4];
            #pragma unroll
            for (int np = 0; np < 2; np++)
                ldsm_x4(bf[np], baseB + (uint32_t)np * 16 * PITCH_H * 2 + kOff);

            #pragma unroll
            for (int mt = 0; mt < 4; mt++)
                #pragma unroll
                for (int nt = 0; nt < 4; nt++)
                    mma_f16(c[mt][nt], a[mt], &bf[nt >> 1][(nt & 1) * 2]);
        }

        // Epilogue: float2 stores (quad-contiguous 32B sectors)
        float* gO = out + (size_t)t * (M_ * M_);
        #pragma unroll
        for (int mt = 0; mt < 4; mt++) {
            const int r0 = mwBase + mt * 16 + g;
            #pragma unroll
            for (int nt = 0; nt < 4; nt++) {
                const int col = nwBase + nt * 8 + tg * 2;
                *(float2*)(gO + (size_t)r0 * M_ + col)       = make_float2(c[mt][nt][0], c[mt][nt][1]);
                *(float2*)(gO + (size_t)(r0 + 8) * M_ + col) = make_float2(c[mt][nt][2], c[mt][nt][3]);
            }
        }

        if (t + 1 < t1) {
            cp_wait0();
            __syncthreads();
            if (qflip) { qcur ^= 1; bi = (t + 1) / I_; }
        }
    }
}

extern "C" void kernel_launch(void* const* d_in, const int* in_sizes, int n_in,
                              void* d_out, int out_size) {
    const float* query   = (const float*)d_in[0];
    const float* support = (const float*)d_in[1];
    float* out = (float*)d_out;

    cudaFuncSetAttribute(cosine_gemm_kernel,
                         cudaFuncAttributeMaxDynamicSharedMemorySize, SMEM_BYTES);

    normalize_kernel<<<(2 * NROWS) / 256, 256>>>(query, support);
    cosine_gemm_kernel<<<NC, 256, SMEM_BYTES>>>(out);
}